// round 16
// baseline (speedup 1.0000x reference)
#include <cuda_runtime.h>
#include <cuda_fp16.h>
#include <math.h>
#include <stdint.h>

// Problem constants
#define BATCH 2
#define SEQ   2048
#define DIM   1024
#define HEADS 16
#define HD    64
#define QKVD  3072   // 3*DIM

// ---------------------------------------------------------------------------
// Global scratch (alloc-free rule). Single fp16 everywhere.
// ---------------------------------------------------------------------------
__device__ __half g_xh [(size_t)BATCH * SEQ * DIM];
__device__ __half g_wqh[(size_t)QKVD * DIM];
__device__ __half g_woh[(size_t)DIM * DIM];
__device__ __half g_qkvh[(size_t)BATCH * SEQ * QKVD];
__device__ __half g_aoh[(size_t)BATCH * SEQ * DIM];

// ============================================================================
// Helpers (generic PTX, compute_103-safe)
// ============================================================================
__device__ __forceinline__ uint32_t smem_u32(const void* p) {
    uint32_t a;
    asm("{ .reg .u64 t; cvta.to.shared.u64 t, %1; cvt.u32.u64 %0, t; }"
        : "=r"(a) : "l"(p));
    return a;
}
__device__ __forceinline__ void ldsm_x4(uint32_t& r0, uint32_t& r1,
                                        uint32_t& r2, uint32_t& r3,
                                        uint32_t addr) {
    asm volatile("ldmatrix.sync.aligned.m8n8.x4.shared.b16 {%0,%1,%2,%3}, [%4];"
                 : "=r"(r0), "=r"(r1), "=r"(r2), "=r"(r3) : "r"(addr));
}
__device__ __forceinline__ void mma_f16(float* d, const uint32_t* a,
                                        const uint32_t* b) {
    asm volatile(
        "mma.sync.aligned.m16n8k16.row.col.f32.f16.f16.f32 "
        "{%0,%1,%2,%3}, {%4,%5,%6,%7}, {%8,%9}, {%0,%1,%2,%3};"
        : "+f"(d[0]), "+f"(d[1]), "+f"(d[2]), "+f"(d[3])
        : "r"(a[0]), "r"(a[1]), "r"(a[2]), "r"(a[3]), "r"(b[0]), "r"(b[1]));
}
__device__ __forceinline__ uint32_t pack2h(float x, float y) {
    __half2 h = __floats2half2_rn(x, y);
    return *(uint32_t*)&h;
}
__device__ __forceinline__ float ex2f(float x) {
    float r;
    asm("ex2.approx.f32 %0, %1;" : "=f"(r) : "f"(x));
    return r;
}
__device__ __forceinline__ void cp16(uint32_t smem, const void* gmem) {
    asm volatile("cp.async.cg.shared.global [%0], [%1], 16;"
                 :: "r"(smem), "l"(gmem));
}
#define CP_COMMIT() asm volatile("cp.async.commit_group;" ::: "memory")
#define CP_WAIT(n)  asm volatile("cp.async.wait_group %0;" :: "n"(n) : "memory")

// ============================================================================
// prep_all: one launch — round x and both weights to fp16.
// ============================================================================
#define XN4  (BATCH * SEQ * DIM / 4)
#define WQ4  (QKVD * DIM / 4)
#define WO4  (DIM * DIM / 4)

__global__ void prep_all(const float* __restrict__ x,
                         const float* __restrict__ wq,
                         const float* __restrict__ wo,
                         __half* __restrict__ xh,
                         __half* __restrict__ wqh, __half* __restrict__ woh) {
    const int stride = gridDim.x * blockDim.x;
    const int base = blockIdx.x * blockDim.x + threadIdx.x;
    for (int i = base; i < XN4; i += stride) {
        float4 v = ((const float4*)x)[i];
        uint2 h;
        h.x = pack2h(v.x, v.y);
        h.y = pack2h(v.z, v.w);
        ((uint2*)xh)[i] = h;
    }
    for (int i = base; i < WQ4; i += stride) {
        float4 v = ((const float4*)wq)[i];
        uint2 h;
        h.x = pack2h(v.x, v.y);
        h.y = pack2h(v.z, v.w);
        ((uint2*)wqh)[i] = h;
    }
    for (int i = base; i < WO4; i += stride) {
        float4 v = ((const float4*)wo)[i];
        uint2 h;
        h.x = pack2h(v.x, v.y);
        h.y = pack2h(v.z, v.w);
        ((uint2*)woh)[i] = h;
    }
}

// ============================================================================
// fp16 GEMM:  C = A @ B^T + bias   (frozen — at legacy-HMMA roofline)
// ============================================================================
#define GKC    64
#define GPITCH 72
#define GA_TILE (128 * GPITCH * 2)
#define GB_TILE (128 * GPITCH * 2)
#define GSTAGE_B (GA_TILE + GB_TILE)
#define G_SMEM_BYTES (2 * GSTAGE_B)

__global__ __launch_bounds__(256, 2) void gemm_f16(
    int M, int N_, int K,
    const __half* __restrict__ Ah,
    const __half* __restrict__ Bh,
    const float* __restrict__ bias,
    float* __restrict__ C,
    __half* __restrict__ Ch)
{
    extern __shared__ __align__(16) char sm[];
    const uint32_t sb0 = smem_u32(sm);

    const int tid = threadIdx.x;
    const int wid = tid >> 5;
    const int lane = tid & 31;
    const int n0 = blockIdx.x * 128;
    const int m0 = blockIdx.y * 128;
    const int warp_m = wid & 3;
    const int warp_n = wid >> 2;

    float acc[2][8][4];
#pragma unroll
    for (int mt = 0; mt < 2; mt++)
#pragma unroll
        for (int nt = 0; nt < 8; nt++)
#pragma unroll
            for (int r = 0; r < 4; r++) acc[mt][nt][r] = 0.0f;

    const int a_row = warp_m * 32 + (lane & 7) + ((lane >> 3) & 1) * 8;
    const int a_kof = ((lane >> 4) & 1) * 8;
    const int b_row = warp_n * 64 + (lane & 7) + ((lane >> 4) & 1) * 8;
    const int b_kof = ((lane >> 3) & 1) * 8;

    const int nchunk = K / GKC;

    auto issue_chunk = [&](int ic, int s) {
        const uint32_t sb = sb0 + (uint32_t)s * GSTAGE_B;
        const int kc = ic * GKC;
#pragma unroll
        for (int i = 0; i < 4; i++) {
            const int id = tid + 256 * i;
            const int row = id >> 3;
            const int c8 = (id & 7) * 8;
            const uint32_t so = (uint32_t)(row * GPITCH + c8) * 2;
            const size_t ga = (size_t)(m0 + row) * K + kc + c8;
            const size_t gb = (size_t)(n0 + row) * K + kc + c8;
            cp16(sb + so,           Ah + ga);
            cp16(sb + GA_TILE + so, Bh + gb);
        }
    };

    issue_chunk(0, 0); CP_COMMIT();

    for (int ic = 0; ic < nchunk; ic++) {
        if (ic + 1 < nchunk) {
            issue_chunk(ic + 1, (ic + 1) & 1); CP_COMMIT();
            CP_WAIT(1);
        } else {
            CP_WAIT(0);
        }
        __syncthreads();

        const uint32_t sb  = sb0 + (uint32_t)(ic & 1) * GSTAGE_B;
        const uint32_t sAh = sb;
        const uint32_t sBh = sb + GA_TILE;

#pragma unroll
        for (int ks = 0; ks < 4; ks++) {
            const int k16 = ks * 16;
            uint32_t ah[2][4];
#pragma unroll
            for (int mt = 0; mt < 2; mt++) {
                const uint32_t aoff =
                    (uint32_t)((a_row + mt * 16) * GPITCH + k16 + a_kof) * 2;
                ldsm_x4(ah[mt][0], ah[mt][1], ah[mt][2], ah[mt][3], sAh + aoff);
            }
            uint32_t bh[8][2];
#pragma unroll
            for (int ntp = 0; ntp < 4; ntp++) {
                const uint32_t boff =
                    (uint32_t)((b_row + ntp * 16) * GPITCH + k16 + b_kof) * 2;
                ldsm_x4(bh[2 * ntp][0], bh[2 * ntp][1],
                        bh[2 * ntp + 1][0], bh[2 * ntp + 1][1], sBh + boff);
            }
#pragma unroll
            for (int mt = 0; mt < 2; mt++)
#pragma unroll
                for (int nt = 0; nt < 8; nt++)
                    mma_f16(acc[mt][nt], ah[mt], bh[nt]);
        }
        __syncthreads();
    }

    // Epilogue
    const int er0 = m0 + warp_m * 32 + (lane >> 2);
    const int ec0 = n0 + warp_n * 64 + (lane & 3) * 2;
#pragma unroll
    for (int mt = 0; mt < 2; mt++) {
#pragma unroll
        for (int nt = 0; nt < 8; nt++) {
            const int col = ec0 + nt * 8;
            const float bx = bias[col], by = bias[col + 1];
            const size_t o0 = (size_t)(er0 + mt * 16) * N_ + col;
            const size_t o1 = (size_t)(er0 + mt * 16 + 8) * N_ + col;
            const float c00 = acc[mt][nt][0] + bx, c01 = acc[mt][nt][1] + by;
            const float c10 = acc[mt][nt][2] + bx, c11 = acc[mt][nt][3] + by;
            if (C) {
                *(float2*)(C + o0) = make_float2(c00, c01);
                *(float2*)(C + o1) = make_float2(c10, c11);
            } else {
                *(uint32_t*)(Ch + o0) = pack2h(c00, c01);
                *(uint32_t*)(Ch + o1) = pack2h(c10, c11);
            }
        }
    }
}

// ============================================================================
// Flash attention, tensor cores, full fp16 operands.
// R16: S(kt+1) MMAs interleaved into softmax(kt)'s latency shadow
// (two S register sets, 3 K smem buffers, loads issued 2 tiles ahead).
// exp via ex2.approx with log2e folded into the scale.
// smem: Qh [128][72]; Kh x3 [64][72]; Vth [64][72]
// ============================================================================
#define APITCH 72
#define A_QTILE (128 * APITCH * 2)     // 18432
#define A_KBUF  (64 * APITCH * 2)      //  9216
#define A_SMEM_BYTES (A_QTILE + 4 * A_KBUF)   // 55296

__global__ __launch_bounds__(256, 1) void attn_tc(
    const __half* __restrict__ qkvh,
    __half* __restrict__ aoh)
{
    extern __shared__ __align__(16) char smema[];
    const uint32_t sQh = smem_u32(smema);
    const uint32_t sK0 = sQh + A_QTILE;            // 3 K buffers from here
    const uint32_t sVth = sK0 + 3 * A_KBUF;
    __half* pVth = (__half*)(smema + A_QTILE + 3 * A_KBUF);

    const int qt = gridDim.x - 1 - blockIdx.x;   // heavy tiles first
    const int h  = blockIdx.y;
    const int b  = blockIdx.z;
    const int tid = threadIdx.x;
    const int wid = tid >> 5;
    const int lane = tid & 31;

    const size_t bN = (size_t)b * SEQ;
    const int qcol = h * HD;
    const int kcol = DIM + h * HD;
    const int vcol = 2 * DIM + h * HD;
    const int ntiles = (qt + 1) * 2;             // always >= 2

    const int vrr = tid >> 2;
    const int vd0 = (tid & 3) * 16;

    auto issue_k = [&](int kt) {
        const uint32_t kbuf = sK0 + (uint32_t)(kt % 3) * A_KBUF;
        const int kb = kt * 64;
#pragma unroll
        for (int i = 0; i < 2; i++) {
            const int id = tid + 256 * i;
            const int row = id >> 3;
            const int c8 = (id & 7) * 8;
            const uint32_t so = (uint32_t)(row * APITCH + c8) * 2;
            const size_t g = (bN + kb + row) * QKVD + kcol + c8;
            cp16(kbuf + so, qkvh + g);
        }
    };

    // ---- Prologue: Q + K0 (group), K1 (group), V0 reg prefetch ----
#pragma unroll
    for (int i = 0; i < 2; i++) {
        const int id = tid + 256 * i;
        const int row = id >> 2;
        const int c8 = (id & 3) * 16;
        const uint32_t so = (uint32_t)(row * APITCH + c8) * 2;
        const size_t g = (bN + qt * 128 + row) * QKVD + qcol + c8;
        cp16(sQh + so,      qkvh + g);
        cp16(sQh + so + 16, qkvh + g + 8);
    }
    issue_k(0);
    CP_COMMIT();           // group: Q + K0
    issue_k(1);
    CP_COMMIT();           // group: K1

    uint4 va, vb;
    {
        const size_t g = (bN + vrr) * QKVD + vcol + vd0;
        va = *(const uint4*)(qkvh + g);
        vb = *(const uint4*)(qkvh + g + 8);
    }

    CP_WAIT(1);            // Q + K0 ready (K1 may be in flight)
    __syncthreads();

    // ---- Hoist Q fragments ----
    const int a_row = wid * 16 + (lane & 7) + ((lane >> 3) & 1) * 8;
    const int a_kof = ((lane >> 4) & 1) * 8;
    uint32_t qh[4][4];
#pragma unroll
    for (int ks = 0; ks < 4; ks++) {
        const uint32_t off = (uint32_t)(a_row * APITCH + ks * 16 + a_kof) * 2;
        ldsm_x4(qh[ks][0], qh[ks][1], qh[ks][2], qh[ks][3], sQh + off);
    }

    const int b_row = (lane & 7) + ((lane >> 4) & 1) * 8;
    const int b_kof = ((lane >> 3) & 1) * 8;

    // S-tile compute (zero + MMA) from a given K buffer
    auto compute_S = [&](float (*s)[4], uint32_t kbuf) {
#pragma unroll
        for (int nt = 0; nt < 8; nt++)
#pragma unroll
            for (int r = 0; r < 4; r++) s[nt][r] = 0.0f;
#pragma unroll
        for (int ks = 0; ks < 4; ks++) {
            uint32_t kh[8][2];
#pragma unroll
            for (int ntp = 0; ntp < 4; ntp++) {
                const uint32_t off =
                    (uint32_t)((ntp * 16 + b_row) * APITCH + ks * 16 + b_kof) * 2;
                ldsm_x4(kh[2 * ntp][0], kh[2 * ntp][1],
                        kh[2 * ntp + 1][0], kh[2 * ntp + 1][1], kbuf + off);
            }
#pragma unroll
            for (int nt = 0; nt < 8; nt++) mma_f16(s[nt], qh[ks], kh[nt]);
        }
    };

    float o[8][4];
#pragma unroll
    for (int nt = 0; nt < 8; nt++)
#pragma unroll
        for (int r = 0; r < 4; r++) o[nt][r] = 0.0f;
    float m0 = -1e30f, m1 = -1e30f, l0 = 0.0f, l1 = 0.0f;

    // scale with log2e folded in (softmax computed in base-2 domain)
    const float qscale = 0.125f * 1.44269504088896f;
    const int row_lo = qt * 128 + wid * 16 + (lane >> 2);
    const int row_hi = row_lo + 8;

    float s_cur[8][4], s_next[8][4];
    compute_S(s_cur, sK0);          // S(0)

    for (int kt = 0; kt < ntiles; kt++) {
        const int kb = kt * 64;
        const bool have1 = (kt + 1 < ntiles);
        const bool have2 = (kt + 2 < ntiles);

        // V(kt) store to smem (transposed); prefetch V(kt+1) regs
        {
            union { uint4 q; __half e[8]; } u0, u1;
            u0.q = va; u1.q = vb;
#pragma unroll
            for (int e = 0; e < 8; e++) {
                pVth[(vd0 + e) * APITCH + vrr]     = u0.e[e];
                pVth[(vd0 + 8 + e) * APITCH + vrr] = u1.e[e];
            }
        }
        uint4 va2 = va, vb2 = vb;
        if (have1) {
            const size_t g = (bN + kb + 64 + vrr) * QKVD + vcol + vd0;
            va2 = *(const uint4*)(qkvh + g);
            vb2 = *(const uint4*)(qkvh + g + 8);
        }

        if (have2) { issue_k(kt + 2); CP_COMMIT(); }
        if (have1) { if (have2) { CP_WAIT(1); } else { CP_WAIT(0); } }
        __syncthreads();   // V(kt) + K(kt+1) visible to all

        // ---- softmax phase 1: scale+mask, row-max (shuffles issued) ----
        const bool full = (kb + 63) <= qt * 128;
        if (full) {
#pragma unroll
            for (int nt = 0; nt < 8; nt++)
#pragma unroll
                for (int r = 0; r < 4; r++) s_cur[nt][r] *= qscale;
        } else {
#pragma unroll
            for (int nt = 0; nt < 8; nt++) {
                const int col = kb + nt * 8 + (lane & 3) * 2;
                s_cur[nt][0] = (col     <= row_lo) ? s_cur[nt][0] * qscale : -1e30f;
                s_cur[nt][1] = (col + 1 <= row_lo) ? s_cur[nt][1] * qscale : -1e30f;
                s_cur[nt][2] = (col     <= row_hi) ? s_cur[nt][2] * qscale : -1e30f;
                s_cur[nt][3] = (col + 1 <= row_hi) ? s_cur[nt][3] * qscale : -1e30f;
            }
        }
        float tm0 = -1e30f, tm1 = -1e30f;
#pragma unroll
        for (int nt = 0; nt < 8; nt++) {
            tm0 = fmaxf(tm0, fmaxf(s_cur[nt][0], s_cur[nt][1]));
            tm1 = fmaxf(tm1, fmaxf(s_cur[nt][2], s_cur[nt][3]));
        }
        tm0 = fmaxf(tm0, __shfl_xor_sync(0xffffffffu, tm0, 1));
        tm1 = fmaxf(tm1, __shfl_xor_sync(0xffffffffu, tm1, 1));
        tm0 = fmaxf(tm0, __shfl_xor_sync(0xffffffffu, tm0, 2));
        tm1 = fmaxf(tm1, __shfl_xor_sync(0xffffffffu, tm1, 2));

        // ---- S(kt+1): independent MMA block fills the latency shadow ----
        if (have1) {
            compute_S(s_next, sK0 + (uint32_t)((kt + 1) % 3) * A_KBUF);
        }

        // ---- softmax phase 2 (base-2 domain) ----
        const float nm0 = fmaxf(m0, tm0);
        const float nm1 = fmaxf(m1, tm1);
        const float corr0 = ex2f(m0 - nm0);
        const float corr1 = ex2f(m1 - nm1);

        float ps0 = 0.0f, ps1 = 0.0f;
#pragma unroll
        for (int nt = 0; nt < 8; nt++) {
            s_cur[nt][0] = ex2f(s_cur[nt][0] - nm0); ps0 += s_cur[nt][0];
            s_cur[nt][1] = ex2f(s_cur[nt][1] - nm0); ps0 += s_cur[nt][1];
            s_cur[nt][2] = ex2f(s_cur[nt][2] - nm1); ps1 += s_cur[nt][2];
            s_cur[nt][3] = ex2f(s_cur[nt][3] - nm1); ps1 += s_cur[nt][3];
        }
        ps0 += __shfl_xor_sync(0xffffffffu, ps0, 1);
        ps1 += __shfl_xor_sync(0xffffffffu, ps1, 1);
        ps0 += __shfl_xor_sync(0xffffffffu, ps0, 2);
        ps1 += __shfl_xor_sync(0xffffffffu, ps1, 2);

        l0 = l0 * corr0 + ps0; m0 = nm0;
        l1 = l1 * corr1 + ps1; m1 = nm1;
#pragma unroll
        for (int nt = 0; nt < 8; nt++) {
            o[nt][0] *= corr0; o[nt][1] *= corr0;
            o[nt][2] *= corr1; o[nt][3] *= corr1;
        }

        // ---- O += P @ V (pack P + load V frags per k-step) ----
#pragma unroll
        for (int ks = 0; ks < 4; ks++) {
            const int j = 2 * ks;
            uint32_t pa[4];
            pa[0] = pack2h(s_cur[j][0],     s_cur[j][1]);
            pa[1] = pack2h(s_cur[j][2],     s_cur[j][3]);
            pa[2] = pack2h(s_cur[j + 1][0], s_cur[j + 1][1]);
            pa[3] = pack2h(s_cur[j + 1][2], s_cur[j + 1][3]);
            uint32_t vh[8][2];
#pragma unroll
            for (int ntp = 0; ntp < 4; ntp++) {
                const uint32_t off =
                    (uint32_t)((ntp * 16 + b_row) * APITCH + ks * 16 + b_kof) * 2;
                ldsm_x4(vh[2 * ntp][0], vh[2 * ntp][1],
                        vh[2 * ntp + 1][0], vh[2 * ntp + 1][1], sVth + off);
            }
#pragma unroll
            for (int nt = 0; nt < 8; nt++) mma_f16(o[nt], pa, vh[nt]);
        }
        __syncthreads();   // protect Vth + K buffer reuse

        if (have1) {
#pragma unroll
            for (int nt = 0; nt < 8; nt++)
#pragma unroll
                for (int r = 0; r < 4; r++) s_cur[nt][r] = s_next[nt][r];
        }
        va = va2; vb = vb2;
    }

    // ---- Epilogue: normalize + fp16 store ----
    const float inv0 = 1.0f / l0;
    const float inv1 = 1.0f / l1;
#pragma unroll
    for (int nt = 0; nt < 8; nt++) {
        const int col = h * HD + nt * 8 + (lane & 3) * 2;
        const size_t o0 = (bN + row_lo) * DIM + col;
        const size_t o1 = (bN + row_hi) * DIM + col;
        *(uint32_t*)(aoh + o0) = pack2h(o[nt][0] * inv0, o[nt][1] * inv0);
        *(uint32_t*)(aoh + o1) = pack2h(o[nt][2] * inv1, o[nt][3] * inv1);
    }
}

// ---------------------------------------------------------------------------
extern "C" void kernel_launch(void* const* d_in, const int* in_sizes, int n_in,
                              void* d_out, int out_size)
{
    const float* x     = (const float*)d_in[0];
    const float* W_qkv = (const float*)d_in[1];
    const float* b_qkv = (const float*)d_in[2];
    const float* W_out = (const float*)d_in[3];
    const float* b_out = (const float*)d_in[4];
    float* out = (float*)d_out;

    __half *xh, *wqh, *woh, *qkvh, *aoh;
    cudaGetSymbolAddress((void**)&xh,  g_xh);
    cudaGetSymbolAddress((void**)&wqh, g_wqh);
    cudaGetSymbolAddress((void**)&woh, g_woh);
    cudaGetSymbolAddress((void**)&qkvh, g_qkvh);
    cudaGetSymbolAddress((void**)&aoh, g_aoh);

    cudaFuncSetAttribute(gemm_f16,
                         cudaFuncAttributeMaxDynamicSharedMemorySize, G_SMEM_BYTES);
    cudaFuncSetAttribute(attn_tc,
                         cudaFuncAttributeMaxDynamicSharedMemorySize, A_SMEM_BYTES);

    const int M = BATCH * SEQ;  // 4096

    // 0) One-launch prep: round x + weights to fp16
    prep_all<<<592, 256>>>(x, W_qkv, W_out, xh, wqh, woh);

    // 1) QKV projection -> fp16 qkv
    {
        dim3 grid(QKVD / 128, M / 128);
        gemm_f16<<<grid, 256, G_SMEM_BYTES>>>(M, QKVD, DIM, xh, wqh,
                                              b_qkv, nullptr, qkvh);
    }
    // 2) Attention -> fp16 aout
    {
        dim3 grid(SEQ / 128, HEADS, BATCH);
        attn_tc<<<grid, 256, A_SMEM_BYTES>>>(qkvh, aoh);
    }
    // 3) Output projection -> fp32 out
    {
        dim3 grid(DIM / 128, M / 128);
        gemm_f16<<<grid, 256, G_SMEM_BYTES>>>(M, DIM, DIM, aoh, woh,
                                              b_out, out, nullptr);
    }
}

// round 17
// speedup vs baseline: 1.0605x; 1.0605x over previous
#include <cuda_runtime.h>
#include <cuda_fp16.h>
#include <math.h>
#include <stdint.h>

// Problem constants
#define BATCH 2
#define SEQ   2048
#define DIM   1024
#define HEADS 16
#define HD    64
#define QKVD  3072   // 3*DIM

// ---------------------------------------------------------------------------
// Global scratch (alloc-free rule). Single fp16 everywhere.
// ---------------------------------------------------------------------------
__device__ __half g_xh [(size_t)BATCH * SEQ * DIM];
__device__ __half g_wqh[(size_t)QKVD * DIM];
__device__ __half g_woh[(size_t)DIM * DIM];
__device__ __half g_qkvh[(size_t)BATCH * SEQ * QKVD];
__device__ __half g_aoh[(size_t)BATCH * SEQ * DIM];

// ============================================================================
// Helpers (generic PTX, compute_103-safe)
// ============================================================================
__device__ __forceinline__ uint32_t smem_u32(const void* p) {
    uint32_t a;
    asm("{ .reg .u64 t; cvta.to.shared.u64 t, %1; cvt.u32.u64 %0, t; }"
        : "=r"(a) : "l"(p));
    return a;
}
__device__ __forceinline__ void ldsm_x4(uint32_t& r0, uint32_t& r1,
                                        uint32_t& r2, uint32_t& r3,
                                        uint32_t addr) {
    asm volatile("ldmatrix.sync.aligned.m8n8.x4.shared.b16 {%0,%1,%2,%3}, [%4];"
                 : "=r"(r0), "=r"(r1), "=r"(r2), "=r"(r3) : "r"(addr));
}
__device__ __forceinline__ void mma_f16(float* d, const uint32_t* a,
                                        const uint32_t* b) {
    asm volatile(
        "mma.sync.aligned.m16n8k16.row.col.f32.f16.f16.f32 "
        "{%0,%1,%2,%3}, {%4,%5,%6,%7}, {%8,%9}, {%0,%1,%2,%3};"
        : "+f"(d[0]), "+f"(d[1]), "+f"(d[2]), "+f"(d[3])
        : "r"(a[0]), "r"(a[1]), "r"(a[2]), "r"(a[3]), "r"(b[0]), "r"(b[1]));
}
__device__ __forceinline__ uint32_t pack2h(float x, float y) {
    __half2 h = __floats2half2_rn(x, y);
    return *(uint32_t*)&h;
}
__device__ __forceinline__ float ex2f(float x) {
    float r;
    asm("ex2.approx.f32 %0, %1;" : "=f"(r) : "f"(x));
    return r;
}
__device__ __forceinline__ void cp16(uint32_t smem, const void* gmem) {
    asm volatile("cp.async.cg.shared.global [%0], [%1], 16;"
                 :: "r"(smem), "l"(gmem));
}
#define CP_COMMIT() asm volatile("cp.async.commit_group;" ::: "memory")
#define CP_WAIT(n)  asm volatile("cp.async.wait_group %0;" :: "n"(n) : "memory")

// ============================================================================
// prep_all: one launch — round x and both weights to fp16.
// ============================================================================
#define XN4  (BATCH * SEQ * DIM / 4)
#define WQ4  (QKVD * DIM / 4)
#define WO4  (DIM * DIM / 4)

__global__ void prep_all(const float* __restrict__ x,
                         const float* __restrict__ wq,
                         const float* __restrict__ wo,
                         __half* __restrict__ xh,
                         __half* __restrict__ wqh, __half* __restrict__ woh) {
    const int stride = gridDim.x * blockDim.x;
    const int base = blockIdx.x * blockDim.x + threadIdx.x;
    for (int i = base; i < XN4; i += stride) {
        float4 v = ((const float4*)x)[i];
        uint2 h;
        h.x = pack2h(v.x, v.y);
        h.y = pack2h(v.z, v.w);
        ((uint2*)xh)[i] = h;
    }
    for (int i = base; i < WQ4; i += stride) {
        float4 v = ((const float4*)wq)[i];
        uint2 h;
        h.x = pack2h(v.x, v.y);
        h.y = pack2h(v.z, v.w);
        ((uint2*)wqh)[i] = h;
    }
    for (int i = base; i < WO4; i += stride) {
        float4 v = ((const float4*)wo)[i];
        uint2 h;
        h.x = pack2h(v.x, v.y);
        h.y = pack2h(v.z, v.w);
        ((uint2*)woh)[i] = h;
    }
}

// ============================================================================
// fp16 GEMM:  C = A @ B^T + bias   (frozen — at legacy-HMMA roofline)
// ============================================================================
#define GKC    64
#define GPITCH 72
#define GA_TILE (128 * GPITCH * 2)
#define GB_TILE (128 * GPITCH * 2)
#define GSTAGE_B (GA_TILE + GB_TILE)
#define G_SMEM_BYTES (2 * GSTAGE_B)

__global__ __launch_bounds__(256, 2) void gemm_f16(
    int M, int N_, int K,
    const __half* __restrict__ Ah,
    const __half* __restrict__ Bh,
    const float* __restrict__ bias,
    float* __restrict__ C,
    __half* __restrict__ Ch)
{
    extern __shared__ __align__(16) char sm[];
    const uint32_t sb0 = smem_u32(sm);

    const int tid = threadIdx.x;
    const int wid = tid >> 5;
    const int lane = tid & 31;
    const int n0 = blockIdx.x * 128;
    const int m0 = blockIdx.y * 128;
    const int warp_m = wid & 3;
    const int warp_n = wid >> 2;

    float acc[2][8][4];
#pragma unroll
    for (int mt = 0; mt < 2; mt++)
#pragma unroll
        for (int nt = 0; nt < 8; nt++)
#pragma unroll
            for (int r = 0; r < 4; r++) acc[mt][nt][r] = 0.0f;

    const int a_row = warp_m * 32 + (lane & 7) + ((lane >> 3) & 1) * 8;
    const int a_kof = ((lane >> 4) & 1) * 8;
    const int b_row = warp_n * 64 + (lane & 7) + ((lane >> 4) & 1) * 8;
    const int b_kof = ((lane >> 3) & 1) * 8;

    const int nchunk = K / GKC;

    auto issue_chunk = [&](int ic, int s) {
        const uint32_t sb = sb0 + (uint32_t)s * GSTAGE_B;
        const int kc = ic * GKC;
#pragma unroll
        for (int i = 0; i < 4; i++) {
            const int id = tid + 256 * i;
            const int row = id >> 3;
            const int c8 = (id & 7) * 8;
            const uint32_t so = (uint32_t)(row * GPITCH + c8) * 2;
            const size_t ga = (size_t)(m0 + row) * K + kc + c8;
            const size_t gb = (size_t)(n0 + row) * K + kc + c8;
            cp16(sb + so,           Ah + ga);
            cp16(sb + GA_TILE + so, Bh + gb);
        }
    };

    issue_chunk(0, 0); CP_COMMIT();

    for (int ic = 0; ic < nchunk; ic++) {
        if (ic + 1 < nchunk) {
            issue_chunk(ic + 1, (ic + 1) & 1); CP_COMMIT();
            CP_WAIT(1);
        } else {
            CP_WAIT(0);
        }
        __syncthreads();

        const uint32_t sb  = sb0 + (uint32_t)(ic & 1) * GSTAGE_B;
        const uint32_t sAh = sb;
        const uint32_t sBh = sb + GA_TILE;

#pragma unroll
        for (int ks = 0; ks < 4; ks++) {
            const int k16 = ks * 16;
            uint32_t ah[2][4];
#pragma unroll
            for (int mt = 0; mt < 2; mt++) {
                const uint32_t aoff =
                    (uint32_t)((a_row + mt * 16) * GPITCH + k16 + a_kof) * 2;
                ldsm_x4(ah[mt][0], ah[mt][1], ah[mt][2], ah[mt][3], sAh + aoff);
            }
            uint32_t bh[8][2];
#pragma unroll
            for (int ntp = 0; ntp < 4; ntp++) {
                const uint32_t boff =
                    (uint32_t)((b_row + ntp * 16) * GPITCH + k16 + b_kof) * 2;
                ldsm_x4(bh[2 * ntp][0], bh[2 * ntp][1],
                        bh[2 * ntp + 1][0], bh[2 * ntp + 1][1], sBh + boff);
            }
#pragma unroll
            for (int mt = 0; mt < 2; mt++)
#pragma unroll
                for (int nt = 0; nt < 8; nt++)
                    mma_f16(acc[mt][nt], ah[mt], bh[nt]);
        }
        __syncthreads();
    }

    // Epilogue
    const int er0 = m0 + warp_m * 32 + (lane >> 2);
    const int ec0 = n0 + warp_n * 64 + (lane & 3) * 2;
#pragma unroll
    for (int mt = 0; mt < 2; mt++) {
#pragma unroll
        for (int nt = 0; nt < 8; nt++) {
            const int col = ec0 + nt * 8;
            const float bx = bias[col], by = bias[col + 1];
            const size_t o0 = (size_t)(er0 + mt * 16) * N_ + col;
            const size_t o1 = (size_t)(er0 + mt * 16 + 8) * N_ + col;
            const float c00 = acc[mt][nt][0] + bx, c01 = acc[mt][nt][1] + by;
            const float c10 = acc[mt][nt][2] + bx, c11 = acc[mt][nt][3] + by;
            if (C) {
                *(float2*)(C + o0) = make_float2(c00, c01);
                *(float2*)(C + o1) = make_float2(c10, c11);
            } else {
                *(uint32_t*)(Ch + o0) = pack2h(c00, c01);
                *(uint32_t*)(Ch + o1) = pack2h(c10, c11);
            }
        }
    }
}

// ============================================================================
// Flash attention, tensor cores, full fp16 operands.
// R17: BKEY=128 (per-tile softmax/barrier overhead amortized over 2x keys),
// base-2 softmax via ex2.approx. Single-buffered V (pitch 136: conflict-free),
// double-buffered K.
// smem: Qh [128][72]; Kh x2 [128][72]; Vth [64][136]
// ============================================================================
#define KPITCH 72
#define VPITCH 136
#define A_QTILE (128 * KPITCH * 2)     // 18432
#define A_KBUF  (128 * KPITCH * 2)     // 18432
#define A_VBUF  (64 * VPITCH * 2)      // 17408
#define A_SMEM_BYTES (A_QTILE + 2 * A_KBUF + A_VBUF)   // 72704

__global__ __launch_bounds__(256, 1) void attn_tc(
    const __half* __restrict__ qkvh,
    __half* __restrict__ aoh)
{
    extern __shared__ __align__(16) char smema[];
    const uint32_t sQh = smem_u32(smema);
    const uint32_t sK0 = sQh + A_QTILE;
    const uint32_t sVth = sK0 + 2 * A_KBUF;
    __half* pVth = (__half*)(smema + A_QTILE + 2 * A_KBUF);

    const int qt = gridDim.x - 1 - blockIdx.x;   // heavy tiles first
    const int h  = blockIdx.y;
    const int b  = blockIdx.z;
    const int tid = threadIdx.x;
    const int wid = tid >> 5;
    const int lane = tid & 31;

    const size_t bN = (size_t)b * SEQ;
    const int qcol = h * HD;
    const int kcol = DIM + h * HD;
    const int vcol = 2 * DIM + h * HD;
    const int ntiles = qt + 1;                  // 128-key tiles

    // V mapping: thread owns key vrr (0..127), dims [vd0, vd0+32)
    const int vrr = tid >> 1;
    const int vd0 = (tid & 1) * 32;

    auto issue_k = [&](int kt) {
        const uint32_t kbuf = sK0 + (uint32_t)(kt & 1) * A_KBUF;
        const int kb = kt * 128;
#pragma unroll
        for (int i = 0; i < 4; i++) {
            const int id = tid + 256 * i;
            const int row = id >> 3;           // 0..127
            const int c8 = (id & 7) * 8;
            const uint32_t so = (uint32_t)(row * KPITCH + c8) * 2;
            const size_t g = (bN + kb + row) * QKVD + kcol + c8;
            cp16(kbuf + so, qkvh + g);
        }
    };

    // ---- Prologue: Q (group1) + K0 (group2) + V0 register prefetch ----
#pragma unroll
    for (int i = 0; i < 2; i++) {
        const int id = tid + 256 * i;
        const int row = id >> 2;
        const int c8 = (id & 3) * 16;
        const uint32_t so = (uint32_t)(row * KPITCH + c8) * 2;
        const size_t g = (bN + qt * 128 + row) * QKVD + qcol + c8;
        cp16(sQh + so,      qkvh + g);
        cp16(sQh + so + 16, qkvh + g + 8);
    }
    CP_COMMIT();
    issue_k(0);
    CP_COMMIT();

    uint4 v0, v1, v2, v3;
    {
        const size_t g = (bN + vrr) * QKVD + vcol + vd0;
        v0 = *(const uint4*)(qkvh + g);
        v1 = *(const uint4*)(qkvh + g + 8);
        v2 = *(const uint4*)(qkvh + g + 16);
        v3 = *(const uint4*)(qkvh + g + 24);
    }

    CP_WAIT(1);            // Q ready; K0 may be in flight
    __syncthreads();

    // ---- Hoist Q fragments ----
    const int a_row = wid * 16 + (lane & 7) + ((lane >> 3) & 1) * 8;
    const int a_kof = ((lane >> 4) & 1) * 8;
    uint32_t qh[4][4];
#pragma unroll
    for (int ks = 0; ks < 4; ks++) {
        const uint32_t off = (uint32_t)(a_row * KPITCH + ks * 16 + a_kof) * 2;
        ldsm_x4(qh[ks][0], qh[ks][1], qh[ks][2], qh[ks][3], sQh + off);
    }

    const int b_row = (lane & 7) + ((lane >> 4) & 1) * 8;
    const int b_kof = ((lane >> 3) & 1) * 8;

    float o[8][4];
#pragma unroll
    for (int nt = 0; nt < 8; nt++)
#pragma unroll
        for (int r = 0; r < 4; r++) o[nt][r] = 0.0f;
    float m0 = -1e30f, m1 = -1e30f, l0 = 0.0f, l1 = 0.0f;

    // base-2 softmax: fold log2(e) into the scale
    const float qscale = 0.125f * 1.44269504088896f;
    const int row_lo = qt * 128 + wid * 16 + (lane >> 2);
    const int row_hi = row_lo + 8;

    for (int kt = 0; kt < ntiles; kt++) {
        const int kb = kt * 128;
        const bool have_next = (kt + 1 < ntiles);

        if (have_next) {
            issue_k(kt + 1);
            CP_COMMIT();
        }

        // Store V(kt) (prefetched) transposed: pVth[dim][key]
        {
            union { uint4 q; __half e[8]; } u0, u1, u2, u3;
            u0.q = v0; u1.q = v1; u2.q = v2; u3.q = v3;
#pragma unroll
            for (int e = 0; e < 8; e++) {
                pVth[(vd0 + e)      * VPITCH + vrr] = u0.e[e];
                pVth[(vd0 + 8 + e)  * VPITCH + vrr] = u1.e[e];
                pVth[(vd0 + 16 + e) * VPITCH + vrr] = u2.e[e];
                pVth[(vd0 + 24 + e) * VPITCH + vrr] = u3.e[e];
            }
        }
        // Prefetch V(kt+1)
        uint4 w0 = v0, w1 = v1, w2 = v2, w3 = v3;
        if (have_next) {
            const size_t g = (bN + kb + 128 + vrr) * QKVD + vcol + vd0;
            w0 = *(const uint4*)(qkvh + g);
            w1 = *(const uint4*)(qkvh + g + 8);
            w2 = *(const uint4*)(qkvh + g + 16);
            w3 = *(const uint4*)(qkvh + g + 24);
        }

        if (have_next) { CP_WAIT(1); } else { CP_WAIT(0); }
        __syncthreads();

        // ---- S = Q @ K^T over 128 keys (16 n-fragments) ----
        const uint32_t sKcur = sK0 + (uint32_t)(kt & 1) * A_KBUF;
        float s[16][4];
#pragma unroll
        for (int nt = 0; nt < 16; nt++)
#pragma unroll
            for (int r = 0; r < 4; r++) s[nt][r] = 0.0f;

#pragma unroll
        for (int ks = 0; ks < 4; ks++) {
            uint32_t kh[16][2];
#pragma unroll
            for (int ntp = 0; ntp < 8; ntp++) {
                const uint32_t off =
                    (uint32_t)((ntp * 16 + b_row) * KPITCH + ks * 16 + b_kof) * 2;
                ldsm_x4(kh[2 * ntp][0], kh[2 * ntp][1],
                        kh[2 * ntp + 1][0], kh[2 * ntp + 1][1], sKcur + off);
            }
#pragma unroll
            for (int nt = 0; nt < 16; nt++) mma_f16(s[nt], qh[ks], kh[nt]);
        }

        // ---- Scale + causal mask (only the diagonal tile kt==qt masks) ----
        const bool full = kt < qt;
        if (full) {
#pragma unroll
            for (int nt = 0; nt < 16; nt++)
#pragma unroll
                for (int r = 0; r < 4; r++) s[nt][r] *= qscale;
        } else {
#pragma unroll
            for (int nt = 0; nt < 16; nt++) {
                const int col = kb + nt * 8 + (lane & 3) * 2;
                s[nt][0] = (col     <= row_lo) ? s[nt][0] * qscale : -1e30f;
                s[nt][1] = (col + 1 <= row_lo) ? s[nt][1] * qscale : -1e30f;
                s[nt][2] = (col     <= row_hi) ? s[nt][2] * qscale : -1e30f;
                s[nt][3] = (col + 1 <= row_hi) ? s[nt][3] * qscale : -1e30f;
            }
        }

        // ---- Online softmax (base-2) ----
        float tm0 = -1e30f, tm1 = -1e30f;
#pragma unroll
        for (int nt = 0; nt < 16; nt++) {
            tm0 = fmaxf(tm0, fmaxf(s[nt][0], s[nt][1]));
            tm1 = fmaxf(tm1, fmaxf(s[nt][2], s[nt][3]));
        }
        tm0 = fmaxf(tm0, __shfl_xor_sync(0xffffffffu, tm0, 1));
        tm1 = fmaxf(tm1, __shfl_xor_sync(0xffffffffu, tm1, 1));
        tm0 = fmaxf(tm0, __shfl_xor_sync(0xffffffffu, tm0, 2));
        tm1 = fmaxf(tm1, __shfl_xor_sync(0xffffffffu, tm1, 2));

        const float nm0 = fmaxf(m0, tm0);
        const float nm1 = fmaxf(m1, tm1);
        const float corr0 = ex2f(m0 - nm0);
        const float corr1 = ex2f(m1 - nm1);

        float ps0 = 0.0f, ps1 = 0.0f;
#pragma unroll
        for (int nt = 0; nt < 16; nt++) {
            s[nt][0] = ex2f(s[nt][0] - nm0); ps0 += s[nt][0];
            s[nt][1] = ex2f(s[nt][1] - nm0); ps0 += s[nt][1];
            s[nt][2] = ex2f(s[nt][2] - nm1); ps1 += s[nt][2];
            s[nt][3] = ex2f(s[nt][3] - nm1); ps1 += s[nt][3];
        }
        ps0 += __shfl_xor_sync(0xffffffffu, ps0, 1);
        ps1 += __shfl_xor_sync(0xffffffffu, ps1, 1);
        ps0 += __shfl_xor_sync(0xffffffffu, ps0, 2);
        ps1 += __shfl_xor_sync(0xffffffffu, ps1, 2);

        l0 = l0 * corr0 + ps0; m0 = nm0;
        l1 = l1 * corr1 + ps1; m1 = nm1;
#pragma unroll
        for (int nt = 0; nt < 8; nt++) {
            o[nt][0] *= corr0; o[nt][1] *= corr0;
            o[nt][2] *= corr1; o[nt][3] *= corr1;
        }

        // ---- O += P @ V (128-key k-dim: 8 k-steps) ----
#pragma unroll
        for (int ks = 0; ks < 8; ks++) {
            const int j = 2 * ks;
            uint32_t pa[4];
            pa[0] = pack2h(s[j][0],     s[j][1]);
            pa[1] = pack2h(s[j][2],     s[j][3]);
            pa[2] = pack2h(s[j + 1][0], s[j + 1][1]);
            pa[3] = pack2h(s[j + 1][2], s[j + 1][3]);
            uint32_t vh[8][2];
#pragma unroll
            for (int ntp = 0; ntp < 4; ntp++) {
                const uint32_t off =
                    (uint32_t)((ntp * 16 + b_row) * VPITCH + ks * 16 + b_kof) * 2;
                ldsm_x4(vh[2 * ntp][0], vh[2 * ntp][1],
                        vh[2 * ntp + 1][0], vh[2 * ntp + 1][1], sVth + off);
            }
#pragma unroll
            for (int nt = 0; nt < 8; nt++) mma_f16(o[nt], pa, vh[nt]);
        }
        __syncthreads();   // protect Vth + K buffer reuse

        v0 = w0; v1 = w1; v2 = w2; v3 = w3;
    }

    // ---- Epilogue: normalize + fp16 store ----
    const float inv0 = 1.0f / l0;
    const float inv1 = 1.0f / l1;
#pragma unroll
    for (int nt = 0; nt < 8; nt++) {
        const int col = h * HD + nt * 8 + (lane & 3) * 2;
        const size_t o0 = (bN + row_lo) * DIM + col;
        const size_t o1 = (bN + row_hi) * DIM + col;
        *(uint32_t*)(aoh + o0) = pack2h(o[nt][0] * inv0, o[nt][1] * inv0);
        *(uint32_t*)(aoh + o1) = pack2h(o[nt][2] * inv1, o[nt][3] * inv1);
    }
}

// ---------------------------------------------------------------------------
extern "C" void kernel_launch(void* const* d_in, const int* in_sizes, int n_in,
                              void* d_out, int out_size)
{
    const float* x     = (const float*)d_in[0];
    const float* W_qkv = (const float*)d_in[1];
    const float* b_qkv = (const float*)d_in[2];
    const float* W_out = (const float*)d_in[3];
    const float* b_out = (const float*)d_in[4];
    float* out = (float*)d_out;

    __half *xh, *wqh, *woh, *qkvh, *aoh;
    cudaGetSymbolAddress((void**)&xh,  g_xh);
    cudaGetSymbolAddress((void**)&wqh, g_wqh);
    cudaGetSymbolAddress((void**)&woh, g_woh);
    cudaGetSymbolAddress((void**)&qkvh, g_qkvh);
    cudaGetSymbolAddress((void**)&aoh, g_aoh);

    cudaFuncSetAttribute(gemm_f16,
                         cudaFuncAttributeMaxDynamicSharedMemorySize, G_SMEM_BYTES);
    cudaFuncSetAttribute(attn_tc,
                         cudaFuncAttributeMaxDynamicSharedMemorySize, A_SMEM_BYTES);

    const int M = BATCH * SEQ;  // 4096

    // 0) One-launch prep: round x + weights to fp16
    prep_all<<<592, 256>>>(x, W_qkv, W_out, xh, wqh, woh);

    // 1) QKV projection -> fp16 qkv
    {
        dim3 grid(QKVD / 128, M / 128);
        gemm_f16<<<grid, 256, G_SMEM_BYTES>>>(M, QKVD, DIM, xh, wqh,
                                              b_qkv, nullptr, qkvh);
    }
    // 2) Attention -> fp16 aout
    {
        dim3 grid(SEQ / 128, HEADS, BATCH);
        attn_tc<<<grid, 256, A_SMEM_BYTES>>>(qkvh, aoh);
    }
    // 3) Output projection -> fp32 out
    {
        dim3 grid(DIM / 128, M / 128);
        gemm_f16<<<grid, 256, G_SMEM_BYTES>>>(M, DIM, DIM, aoh, woh,
                                              b_out, out, nullptr);
    }
}